// round 16
// baseline (speedup 1.0000x reference)
#include <cuda_runtime.h>
#include <cuda_bf16.h>
#include <cstdint>
#include <math.h>

#define MAX_N 131072

// Scratch + pre-split fragment weights (allocation-free rule)
__device__ float g_phi0[MAX_N];
__device__ float g_vals[3 * MAX_N];
// [net][(layer*8+kt)*512 + nt*32 + lane] = {bh0, bh1, bl0, bl1}
__device__ uint4 g_wfrag[2][12288];

// ---------------------------------------------------------------------------
__device__ __forceinline__ uint32_t pack_bf16(float a, float b) {
    __nv_bfloat162 h = __floats2bfloat162_rn(a, b);
    return *reinterpret_cast<uint32_t*>(&h);
}

__device__ __forceinline__ float fast_tanh(float x) {
    float ax = fabsf(x);
    float e  = __expf(-2.0f * ax);
    float t  = __fdividef(1.0f - e, 1.0f + e);
    return copysignf(t, x);
}

__device__ __forceinline__ void mma_bf16(float c[4],
                                         const uint32_t a[4],
                                         uint32_t b0, uint32_t b1) {
    asm volatile(
        "mma.sync.aligned.m16n8k16.row.col.f32.bf16.bf16.f32 "
        "{%0,%1,%2,%3}, {%4,%5,%6,%7}, {%8,%9}, {%0,%1,%2,%3};"
        : "+f"(c[0]), "+f"(c[1]), "+f"(c[2]), "+f"(c[3])
        : "r"(a[0]), "r"(a[1]), "r"(a[2]), "r"(a[3]), "r"(b0), "r"(b1));
}

// ---------------------------------------------------------------------------
// Prep: split Wh (3 x 128 x 128 fp32, [k][n]) into frag-ordered bf16 hi/lo.
// grid = 24 blocks (layer*8 + kt), 512 threads (nt*32 + lane).
// B frag (m16n8k16 col): n = 8*nt + lane/4 ; k = 16*kt + 2*(lane%4) (+1, +8, +9)
// ---------------------------------------------------------------------------
__global__ void prep_kernel(const float* __restrict__ Wh, int net) {
    int bid   = blockIdx.x;          // layer*8 + kt
    int layer = bid >> 3, kt = bid & 7;
    int t     = threadIdx.x;         // nt*32 + lane
    int lane  = t & 31;
    int nn    = 8 * (t >> 5) + (lane >> 2);
    int k0    = 16 * kt + 2 * (lane & 3);
    const float* W = Wh + layer * 16384;

    float w00 = W[k0 * 128 + nn];
    float w01 = W[(k0 + 1) * 128 + nn];
    float w10 = W[(k0 + 8) * 128 + nn];
    float w11 = W[(k0 + 9) * 128 + nn];

    float l00 = w00 - __bfloat162float(__float2bfloat16(w00));
    float l01 = w01 - __bfloat162float(__float2bfloat16(w01));
    float l10 = w10 - __bfloat162float(__float2bfloat16(w10));
    float l11 = w11 - __bfloat162float(__float2bfloat16(w11));

    uint4 out;
    out.x = pack_bf16(w00, w01);
    out.y = pack_bf16(w10, w11);
    out.z = pack_bf16(l00, l01);
    out.w = pack_bf16(l10, l11);
    g_wfrag[net][bid * 512 + t] = out;
}

// ---------------------------------------------------------------------------
// Main persistent kernel. 384 threads = 12 warps (3 per SMSP).
// MMA stream is pass-ordered over groups of 4 accumulators so consecutive
// (volatile, hence unreorderable) HMMAs never share a C-fragment:
// dependency distance 4 instead of back-to-back RAW chains of 3.
// Per-accumulator order (hi*Whi -> lo*Whi -> hi*Wlo) is unchanged => numerics
// are bit-identical to the R9/R11 kernels.
// ---------------------------------------------------------------------------
#define SMEM_BYTES (12288 * 16 + (768 + 128 + 384 + 128) * 4)   // 202240
#define NWARP 12
#define NTHR  (NWARP * 32)

template <int IN_DIM, int IS_DP>
__global__ __launch_bounds__(NTHR, 1)
void mlp_mma_kernel(const float* __restrict__ tx,
                    const float* __restrict__ W0, const float* __restrict__ b0,
                    const float* __restrict__ bh, const float* __restrict__ Wo,
                    const float* __restrict__ bo,
                    int n, int net)
{
    extern __shared__ char sm[];
    uint4* sW  = (uint4*)sm;               // 12288 entries
    float* sW0 = (float*)(sW + 12288);     // IN_DIM*128
    float* sB0 = sW0 + 768;                // 128
    float* sBh = sB0 + 128;                // 384
    float* sWo = sBh + 384;                // 128

    const int tid = threadIdx.x;
    {
        const uint4* src = g_wfrag[net];
        for (int i = tid; i < 12288; i += NTHR) sW[i] = src[i];
        for (int i = tid; i < IN_DIM * 128; i += NTHR) sW0[i] = W0[i];
        if (tid < 128) {
            sB0[tid] = b0[tid];
            sWo[tid] = Wo[tid];
            sBh[tid] = bh[tid];
            sBh[128 + tid] = bh[128 + tid];
            sBh[256 + tid] = bh[256 + tid];
        }
    }
    __syncthreads();

    const int warp   = tid >> 5;
    const int lane   = tid & 31;
    const int q2     = 2 * (lane & 3);     // C/A col offset within 8-wide tile
    const int rofs   = lane >> 2;          // row within 16-row chunk (and +8)
    const float bo0  = __ldg(bo);
    const int cpn    = n >> 4;             // 16-row chunks per GL node
    const int nchunks = IS_DP ? 3 * cpn : cpn;
    const int wstep  = gridDim.x * NWARP;

    // incremental node-index tracking (avoids div in the loop)
    int ch0 = blockIdx.x * NWARP + warp;
    int g   = 0;
    if (IS_DP) { while (g < 2 && ch0 >= (g + 1) * cpn) ++g; }

    for (int ch = ch0; ch < nchunks; ch += wstep) {
        int idx = ch;
        float nf = 0.0f;
        if (IS_DP) {
            while (g < 2 && ch >= (g + 1) * cpn) ++g;
            idx = ch - g * cpn;
            const float SQ = 0.7745966692414834f;
            nf = (g == 0) ? 0.5f * (1.0f - SQ) : (g == 1) ? 0.5f : 0.5f * (1.0f + SQ);
        }
        const int rA = (idx << 4) + rofs;             // rows rA and rA+8

        // ---- features for both owned rows (fully unrolled -> registers) ----
        float zA[IN_DIM], zB[IN_DIM];
        #pragma unroll
        for (int half = 0; half < 2; ++half) {
            float* z = half ? zB : zA;
            float4 p = *(const float4*)(tx + 4 * (rA + 8 * half));
            float xx = p.y, yy = p.z, zz = p.w;
            float r2  = fmaf(xx, xx, yy * yy);
            float r   = sqrtf(fmaf(zz, zz, r2) + 1e-8f);
            float rho = sqrtf(r2 + 1e-8f);
            float ir  = __fdividef(1.0f, r);
            float irh = __fdividef(1.0f, rho);
            int o = 0;
            if (IS_DP) z[o++] = p.x * nf;
            z[o++] = __fdividef(r, 1.0f + r);
            z[o++] = zz * ir;
            z[o++] = rho * ir;
            z[o++] = xx * irh;
            z[o++] = yy * irh;
        }

        // ---- layer 0 (scalar fp32): v[nt][{0,1}] rows rA, v[nt][{2,3}] rows rA+8
        float v[16][4];
        #pragma unroll
        for (int nt = 0; nt < 16; ++nt) {
            float2 bb = *(const float2*)(sB0 + 8 * nt + q2);
            v[nt][0] = bb.x; v[nt][1] = bb.y; v[nt][2] = bb.x; v[nt][3] = bb.y;
        }
        #pragma unroll
        for (int k = 0; k < IN_DIM; ++k) {
            float a = zA[k], b = zB[k];
            const float* wr = sW0 + k * 128 + q2;
            #pragma unroll
            for (int nt = 0; nt < 16; ++nt) {
                float2 w = *(const float2*)(wr + 8 * nt);
                v[nt][0] = fmaf(a, w.x, v[nt][0]);
                v[nt][1] = fmaf(a, w.y, v[nt][1]);
                v[nt][2] = fmaf(b, w.x, v[nt][2]);
                v[nt][3] = fmaf(b, w.y, v[nt][3]);
            }
        }
        #pragma unroll
        for (int nt = 0; nt < 16; ++nt)
            #pragma unroll
            for (int j = 0; j < 4; ++j) v[nt][j] = fast_tanh(v[nt][j]);

        // ---- 3 hidden layers on tensor cores (register-resident activations)
        #pragma unroll 1
        for (int l = 0; l < 3; ++l) {
            // accum init = bias
            float c[16][4];
            const float* blp = sBh + l * 128 + q2;
            #pragma unroll
            for (int nt = 0; nt < 16; ++nt) {
                float2 bb = *(const float2*)(blp + 8 * nt);
                c[nt][0] = bb.x; c[nt][1] = bb.y; c[nt][2] = bb.x; c[nt][3] = bb.y;
            }
            const uint4* wl = sW + l * 4096 + lane;
            #pragma unroll
            for (int kt = 0; kt < 8; ++kt) {
                // on-the-fly split of v[2kt], v[2kt+1] into the kt A-fragment
                uint32_t AH[4], AL[4];
                #pragma unroll
                for (int t2 = 0; t2 < 2; ++t2) {
                    int nt = 2 * kt + t2;
                    #pragma unroll
                    for (int jj = 0; jj < 2; ++jj) {
                        float a = v[nt][2 * jj], b = v[nt][2 * jj + 1];
                        uint32_t h = pack_bf16(a, b);
                        __nv_bfloat162 hb = *reinterpret_cast<__nv_bfloat162*>(&h);
                        float ra = a - __bfloat162float(hb.x);
                        float rb = b - __bfloat162float(hb.y);
                        AH[t2 * 2 + jj] = h;
                        AL[t2 * 2 + jj] = pack_bf16(ra, rb);
                    }
                }
                // pass-ordered MMAs over groups of 4 accumulators:
                // consecutive volatile HMMAs target distinct C-frags
                #pragma unroll
                for (int ntg = 0; ntg < 4; ++ntg) {
                    const int nb = 4 * ntg;
                    uint4 b0 = wl[(kt * 16 + nb + 0) * 32];
                    uint4 b1 = wl[(kt * 16 + nb + 1) * 32];
                    uint4 b2 = wl[(kt * 16 + nb + 2) * 32];
                    uint4 b3 = wl[(kt * 16 + nb + 3) * 32];
                    // pass 1: hi * Whi
                    mma_bf16(c[nb + 0], AH, b0.x, b0.y);
                    mma_bf16(c[nb + 1], AH, b1.x, b1.y);
                    mma_bf16(c[nb + 2], AH, b2.x, b2.y);
                    mma_bf16(c[nb + 3], AH, b3.x, b3.y);
                    // pass 2: lo * Whi
                    mma_bf16(c[nb + 0], AL, b0.x, b0.y);
                    mma_bf16(c[nb + 1], AL, b1.x, b1.y);
                    mma_bf16(c[nb + 2], AL, b2.x, b2.y);
                    mma_bf16(c[nb + 3], AL, b3.x, b3.y);
                    // pass 3: hi * Wlo
                    mma_bf16(c[nb + 0], AH, b0.z, b0.w);
                    mma_bf16(c[nb + 1], AH, b1.z, b1.w);
                    mma_bf16(c[nb + 2], AH, b2.z, b2.w);
                    mma_bf16(c[nb + 3], AH, b3.z, b3.w);
                }
            }
            #pragma unroll
            for (int nt = 0; nt < 16; ++nt)
                #pragma unroll
                for (int j = 0; j < 4; ++j) v[nt][j] = fast_tanh(c[nt][j]);
        }

        // ---- output layer: dot with Wo, reduce over the 4 lanes of the group
        float sA = 0.0f, sB = 0.0f;
        #pragma unroll
        for (int nt = 0; nt < 16; ++nt) {
            float2 w = *(const float2*)(sWo + 8 * nt + q2);
            sA = fmaf(v[nt][0], w.x, fmaf(v[nt][1], w.y, sA));
            sB = fmaf(v[nt][2], w.x, fmaf(v[nt][3], w.y, sB));
        }
        sA += __shfl_xor_sync(0xffffffffu, sA, 1);
        sA += __shfl_xor_sync(0xffffffffu, sA, 2);
        sB += __shfl_xor_sync(0xffffffffu, sB, 1);
        sB += __shfl_xor_sync(0xffffffffu, sB, 2);
        if ((lane & 3) == 0) {
            float* dst = IS_DP ? (g_vals + g * n) : g_phi0;
            dst[rA]     = sA + bo0;
            dst[rA + 8] = sB + bo0;
        }
    }
}

// ---------------------------------------------------------------------------
__global__ void combine_kernel(const float* __restrict__ tx,
                               float* __restrict__ out, int n)
{
    int i = blockIdx.x * blockDim.x + threadIdx.x;
    if (i >= n) return;
    const float wA = 5.0f / 9.0f;
    const float wB = 8.0f / 9.0f;
    float s = wA * (g_vals[i] + g_vals[2 * n + i]) + wB * g_vals[n + i];
    float t = tx[4 * i];
    out[i] = g_phi0[i] + 0.5f * t * s;
}

// ---------------------------------------------------------------------------
// inputs: 0 tx | 1..6 dp_{W0,b0,Wh,bh,Wo,bo} | 7..12 ic_{...}
// ---------------------------------------------------------------------------
extern "C" void kernel_launch(void* const* d_in, const int* in_sizes, int n_in,
                              void* d_out, int out_size)
{
    const float* tx   = (const float*)d_in[0];
    const float* dpW0 = (const float*)d_in[1];
    const float* dpb0 = (const float*)d_in[2];
    const float* dpWh = (const float*)d_in[3];
    const float* dpbh = (const float*)d_in[4];
    const float* dpWo = (const float*)d_in[5];
    const float* dpbo = (const float*)d_in[6];
    const float* icW0 = (const float*)d_in[7];
    const float* icb0 = (const float*)d_in[8];
    const float* icWh = (const float*)d_in[9];
    const float* icbh = (const float*)d_in[10];
    const float* icWo = (const float*)d_in[11];
    const float* icbo = (const float*)d_in[12];

    int n = in_sizes[0] / 4;   // 131072

    int smc = 148;
    cudaDeviceGetAttribute(&smc, cudaDevAttrMultiProcessorCount, 0);

    cudaFuncSetAttribute(mlp_mma_kernel<5, 0>,
                         cudaFuncAttributeMaxDynamicSharedMemorySize, SMEM_BYTES);
    cudaFuncSetAttribute(mlp_mma_kernel<6, 1>,
                         cudaFuncAttributeMaxDynamicSharedMemorySize, SMEM_BYTES);

    // pre-split weights into fragment order (net 0 = ic, net 1 = dp)
    prep_kernel<<<24, 512>>>(icWh, 0);
    prep_kernel<<<24, 512>>>(dpWh, 1);

    // ic: phi0, 5 features
    mlp_mma_kernel<5, 0><<<smc, NTHR, SMEM_BYTES>>>(
        tx, icW0, icb0, icbh, icWo, icbo, n, 0);
    // dp: 3 GL nodes, 6 features
    mlp_mma_kernel<6, 1><<<smc, NTHR, SMEM_BYTES>>>(
        tx, dpW0, dpb0, dpbh, dpWo, dpbo, n, 1);
    // Gauss-Legendre combine
    combine_kernel<<<(n + 255) / 256, 256>>>(tx, (float*)d_out, n);
}